// round 1
// baseline (speedup 1.0000x reference)
#include <cuda_runtime.h>
#include <cuda_bf16.h>
#include <math.h>

#define BATCH   8192
#define IN_DIM  512
#define EMB     64
#define KC      256
#define DENSE   1152

// ---------------- scratch (device globals: no allocation allowed) ----------------
__device__ float g_h1[BATCH * DENSE];
__device__ float g_h2[BATCH * DENSE];
__device__ float g_enc[BATCH * EMB];
__device__ float g_quant[BATCH * EMB];
__device__ float g_Linv[KC * EMB * EMB];   // inverse of chol(cov + eps I), lower, upper zeroed
__device__ float g_Lraw[KC * EMB * EMB];   // chol(cov), lower, upper zeroed
__device__ float g_logdet[KC];
__device__ float g_lp[BATCH * KC];
__device__ int   g_idx[BATCH];

__device__ __forceinline__ float selu_f(float x) {
    const float scale = 1.0507009873554805f;
    const float alpha = 1.6732632423543772f;
    return scale * (x > 0.f ? x : alpha * expm1f(x));
}

// ---------------- SGEMM: C = A[M,K] @ W[N,K]^T + bias, optional SELU ----------------
template<int BM, int BN, int BK, int TM, int TN, bool SELU_ACT>
__global__ void __launch_bounds__(256) sgemm_kernel(
    const float* __restrict__ A, const float* __restrict__ W,
    const float* __restrict__ bias, float* __restrict__ C,
    int M, int N, int K)
{
    __shared__ float As[BK][BM];
    __shared__ float Ws[BK][BN];

    const int tid = threadIdx.x;
    const int tx = tid % (BN / TN);
    const int ty = tid / (BN / TN);
    const int bm = blockIdx.y * BM;
    const int bn = blockIdx.x * BN;

    float acc[TM][TN];
#pragma unroll
    for (int i = 0; i < TM; i++)
#pragma unroll
        for (int j = 0; j < TN; j++) acc[i][j] = 0.f;

    for (int k0 = 0; k0 < K; k0 += BK) {
        // load A tile (BM x BK) as float4, store transposed As[k][m]
        for (int n = tid; n < (BM * BK) / 4; n += 256) {
            int row = n / (BK / 4);
            int cb  = n % (BK / 4);
            float4 v = *(const float4*)(A + (size_t)(bm + row) * K + k0 + cb * 4);
            As[cb * 4 + 0][row] = v.x;
            As[cb * 4 + 1][row] = v.y;
            As[cb * 4 + 2][row] = v.z;
            As[cb * 4 + 3][row] = v.w;
        }
        for (int n = tid; n < (BN * BK) / 4; n += 256) {
            int row = n / (BK / 4);
            int cb  = n % (BK / 4);
            float4 v = *(const float4*)(W + (size_t)(bn + row) * K + k0 + cb * 4);
            Ws[cb * 4 + 0][row] = v.x;
            Ws[cb * 4 + 1][row] = v.y;
            Ws[cb * 4 + 2][row] = v.z;
            Ws[cb * 4 + 3][row] = v.w;
        }
        __syncthreads();

#pragma unroll
        for (int kk = 0; kk < BK; kk++) {
            float a[TM], b[TN];
#pragma unroll
            for (int i = 0; i < TM; i++) a[i] = As[kk][ty * TM + i];
#pragma unroll
            for (int j = 0; j < TN; j++) b[j] = Ws[kk][tx * TN + j];
#pragma unroll
            for (int i = 0; i < TM; i++)
#pragma unroll
                for (int j = 0; j < TN; j++)
                    acc[i][j] = fmaf(a[i], b[j], acc[i][j]);
        }
        __syncthreads();
    }

#pragma unroll
    for (int i = 0; i < TM; i++) {
        int m = bm + ty * TM + i;
#pragma unroll
        for (int j = 0; j < TN; j++) {
            int n = bn + tx * TN + j;
            float v = acc[i][j] + bias[n];
            if (SELU_ACT) v = selu_f(v);
            C[(size_t)m * N + n] = v;
        }
    }
}

// ---------------- Cholesky (+ optional inverse & logdet) ----------------
// blocks 0..255:   L = chol(cov_k + eps I) -> Linv (lower, upper zeroed), logdet
// blocks 256..511: L = chol(cov_k)         -> Lraw (lower, upper zeroed)
__global__ void chol_kernel(const float* __restrict__ cov) {
    __shared__ float Ls[EMB][EMB + 1];
    __shared__ float Inv[EMB][EMB + 1];

    const int k   = blockIdx.x & (KC - 1);
    const bool raw = blockIdx.x >= KC;
    const int i = threadIdx.x;   // 0..63
    const float* A = cov + (size_t)k * EMB * EMB;

    for (int j = 0; j < EMB; j++) Ls[i][j] = A[i * EMB + j];
    if (!raw) Ls[i][i] += 0.005f;
    __syncthreads();

    for (int j = 0; j < EMB; j++) {
        if (i == j) {
            float s = Ls[j][j];
            for (int t = 0; t < j; t++) s -= Ls[j][t] * Ls[j][t];
            Ls[j][j] = sqrtf(s);
        }
        __syncthreads();
        if (i > j) {
            float s = Ls[i][j];
            for (int t = 0; t < j; t++) s -= Ls[i][t] * Ls[j][t];
            Ls[i][j] = s / Ls[j][j];
        }
        __syncthreads();
    }

    if (raw) {
        float* out = g_Lraw + (size_t)k * EMB * EMB;
        for (int j = 0; j < EMB; j++) out[i * EMB + j] = (j <= i) ? Ls[i][j] : 0.f;
    } else {
        if (i == 0) {
            float ld = 0.f;
            for (int t = 0; t < EMB; t++) ld += logf(Ls[t][t]);
            g_logdet[k] = 2.f * ld;
        }
        // thread i = column c of L^{-1}: forward substitution (independent per column)
        const int c = i;
        for (int r = 0; r < EMB; r++) {
            if (r < c) { Inv[r][c] = 0.f; continue; }
            float s = (r == c) ? 1.f : 0.f;
            for (int t = c; t < r; t++) s -= Ls[r][t] * Inv[t][c];
            Inv[r][c] = s / Ls[r][r];
        }
        __syncthreads();
        float* out = g_Linv + (size_t)k * EMB * EMB;
        for (int j = 0; j < EMB; j++) out[i * EMB + j] = Inv[i][j];
    }
}

// ---------------- log-probs: grid (b-tiles of 128, K), block 128 ----------------
__global__ void __launch_bounds__(128) logprob_kernel(
    const float* __restrict__ means, const float* __restrict__ sizes)
{
    __shared__ float sLinv[EMB * EMB];
    __shared__ float smean[EMB];

    const int k = blockIdx.y;
    const int b = blockIdx.x * 128 + threadIdx.x;
    const float* Lk = g_Linv + (size_t)k * EMB * EMB;

    for (int i = threadIdx.x; i < (EMB * EMB) / 4; i += 128)
        ((float4*)sLinv)[i] = ((const float4*)Lk)[i];
    if (threadIdx.x < EMB) smean[threadIdx.x] = means[k * EMB + threadIdx.x];
    __syncthreads();

    float diff[EMB];
    const float4* er = (const float4*)(g_enc + (size_t)b * EMB);
#pragma unroll
    for (int t = 0; t < EMB / 4; t++) {
        float4 e = er[t];
        diff[4 * t + 0] = e.x - smean[4 * t + 0];
        diff[4 * t + 1] = e.y - smean[4 * t + 1];
        diff[4 * t + 2] = e.z - smean[4 * t + 2];
        diff[4 * t + 3] = e.w - smean[4 * t + 3];
    }

    float quad = 0.f;
#pragma unroll
    for (int d = 0; d < EMB; d++) {
        float s = 0.f;
#pragma unroll
        for (int t4 = 0; t4 <= d; t4 += 4) {   // upper part of Linv is zero -> safe padding
            float4 lv = *(const float4*)(sLinv + d * EMB + t4);
            s += lv.x * diff[t4 + 0];
            s += lv.y * diff[t4 + 1];
            s += lv.z * diff[t4 + 2];
            s += lv.w * diff[t4 + 3];
        }
        quad += s * s;
    }

    const float LOG2PI = 1.8378770664093453f;
    float lp = logf(sizes[k]) - 0.5f * (64.f * LOG2PI + g_logdet[k]) - 0.5f * quad;
    g_lp[(size_t)b * KC + k] = lp;
}

// ---------------- argmax over K per row (one warp per row) ----------------
__global__ void argmax_kernel() {
    int gwarp = (blockIdx.x * blockDim.x + threadIdx.x) >> 5;
    int lane  = threadIdx.x & 31;
    if (gwarp >= BATCH) return;

    float best = -INFINITY;
    int bi = 0;
    const float* row = g_lp + (size_t)gwarp * KC;
    for (int k = lane; k < KC; k += 32) {
        float v = row[k];
        if (v > best || (v == best && k < bi)) { best = v; bi = k; }
    }
#pragma unroll
    for (int off = 16; off; off >>= 1) {
        float ov = __shfl_down_sync(0xffffffffu, best, off);
        int   oi = __shfl_down_sync(0xffffffffu, bi, off);
        if (ov > best || (ov == best && oi < bi)) { best = ov; bi = oi; }
    }
    if (lane == 0) g_idx[gwarp] = bi;
}

// ---------------- sample: quantized[b] = means[idx] + Lraw[idx] @ noise[b] ----------------
__global__ void __launch_bounds__(64) sample_kernel(
    const float* __restrict__ noise, const float* __restrict__ means)
{
    __shared__ float sL[EMB * EMB];
    __shared__ float sn[EMB];
    const int b = blockIdx.x;
    const int t = threadIdx.x;
    const int k = g_idx[b];
    const float* L = g_Lraw + (size_t)k * EMB * EMB;

    for (int i = t; i < (EMB * EMB) / 4; i += 64)
        ((float4*)sL)[i] = ((const float4*)L)[i];
    sn[t] = noise[(size_t)b * EMB + t];
    __syncthreads();

    float s = means[k * EMB + t];
    for (int j = 0; j <= t; j++) s += sL[t * EMB + j] * sn[j];
    g_quant[(size_t)b * EMB + t] = s;   // straight-through: forward value == sample
}

// ---------------- pack log_probs + idx into output tail ----------------
__global__ void pack_kernel(float* __restrict__ out, int out_size) {
    const int LP_OFF  = BATCH * IN_DIM;           // 4194304
    const int IDX_OFF = LP_OFF + BATCH * KC;      // 6291456
    int i = blockIdx.x * blockDim.x + threadIdx.x;
    if (out_size >= IDX_OFF && i < BATCH * KC)
        out[LP_OFF + i] = g_lp[i];
    if (out_size >= IDX_OFF + BATCH && i < BATCH)
        out[IDX_OFF + i] = (float)g_idx[i];
}

// ---------------- launch ----------------
extern "C" void kernel_launch(void* const* d_in, const int* in_sizes, int n_in,
                              void* d_out, int out_size)
{
    const float* x     = (const float*)d_in[0];
    const float* noise = (const float*)d_in[1];
    const float* eW1 = (const float*)d_in[2];
    const float* eb1 = (const float*)d_in[3];
    const float* eW2 = (const float*)d_in[4];
    const float* eb2 = (const float*)d_in[5];
    const float* eW3 = (const float*)d_in[6];
    const float* eb3 = (const float*)d_in[7];
    const float* dW1 = (const float*)d_in[8];
    const float* db1 = (const float*)d_in[9];
    const float* dW2 = (const float*)d_in[10];
    const float* db2 = (const float*)d_in[11];
    const float* dW3 = (const float*)d_in[12];
    const float* db3 = (const float*)d_in[13];
    const float* means = (const float*)d_in[14];
    const float* sizes = (const float*)d_in[15];
    const float* cov   = (const float*)d_in[16];
    float* out = (float*)d_out;

    float *h1, *h2, *enc, *quant;
    cudaGetSymbolAddress((void**)&h1, g_h1);
    cudaGetSymbolAddress((void**)&h2, g_h2);
    cudaGetSymbolAddress((void**)&enc, g_enc);
    cudaGetSymbolAddress((void**)&quant, g_quant);

    // GMM prep (independent of encoder — launch first)
    chol_kernel<<<2 * KC, EMB>>>(cov);

    // encoder
    sgemm_kernel<128, 128, 8, 8, 8, true><<<dim3(DENSE / 128, BATCH / 128), 256>>>(
        x, eW1, eb1, h1, BATCH, DENSE, IN_DIM);
    sgemm_kernel<128, 128, 8, 8, 8, true><<<dim3(DENSE / 128, BATCH / 128), 256>>>(
        h1, eW2, eb2, h2, BATCH, DENSE, DENSE);
    sgemm_kernel<64, 64, 16, 4, 4, false><<<dim3(EMB / 64, BATCH / 64), 256>>>(
        h2, eW3, eb3, enc, BATCH, EMB, DENSE);

    // GMM log-probs + argmax + sample
    logprob_kernel<<<dim3(BATCH / 128, KC), 128>>>(means, sizes);
    argmax_kernel<<<(BATCH * 32) / 256, 256>>>();
    sample_kernel<<<BATCH, EMB>>>(noise, means);

    // decoder (dec straight into out[0 .. B*IN_DIM))
    sgemm_kernel<128, 128, 8, 8, 8, true><<<dim3(DENSE / 128, BATCH / 128), 256>>>(
        quant, dW1, db1, h1, BATCH, DENSE, EMB);
    sgemm_kernel<128, 128, 8, 8, 8, true><<<dim3(DENSE / 128, BATCH / 128), 256>>>(
        h1, dW2, db2, h2, BATCH, DENSE, DENSE);
    sgemm_kernel<128, 128, 8, 8, 8, false><<<dim3(IN_DIM / 128, BATCH / 128), 256>>>(
        h2, dW3, db3, out, BATCH, IN_DIM, DENSE);

    // tail outputs
    pack_kernel<<<(BATCH * KC + 255) / 256, 256>>>(out, out_size);
}

// round 2
// speedup vs baseline: 1.0010x; 1.0010x over previous
#include <cuda_runtime.h>
#include <cuda_bf16.h>
#include <math.h>

#define BATCH   8192
#define IN_DIM  512
#define EMB     64
#define KC      256
#define DENSE   1152

// ---------------- scratch (device globals: no allocation allowed) ----------------
__device__ float g_h1[BATCH * DENSE];
__device__ float g_h2[BATCH * DENSE];
__device__ float g_enc[BATCH * EMB];
__device__ float g_quant[BATCH * EMB];
__device__ float g_Linv[KC * EMB * EMB];   // inverse of chol(cov + eps I), lower, upper zeroed
__device__ float g_Lraw[KC * EMB * EMB];   // chol(cov), lower, upper zeroed
__device__ float g_logdet[KC];
__device__ float g_lp[BATCH * KC];
__device__ int   g_idx[BATCH];

__device__ __forceinline__ float selu_f(float x) {
    const float scale = 1.0507009873554805f;
    const float alpha = 1.6732632423543772f;
    return scale * (x > 0.f ? x : alpha * expm1f(x));
}

// ---------------- SGEMM: C = A[M,K] @ W[N,K]^T + bias, optional SELU ----------------
template<int BM, int BN, int BK, int TM, int TN, bool SELU_ACT>
__global__ void __launch_bounds__(256) sgemm_kernel(
    const float* __restrict__ A, const float* __restrict__ W,
    const float* __restrict__ bias, float* __restrict__ C,
    int M, int N, int K)
{
    __shared__ float As[BK][BM];
    __shared__ float Ws[BK][BN];

    const int tid = threadIdx.x;
    const int tx = tid % (BN / TN);
    const int ty = tid / (BN / TN);
    const int bm = blockIdx.y * BM;
    const int bn = blockIdx.x * BN;

    float acc[TM][TN];
#pragma unroll
    for (int i = 0; i < TM; i++)
#pragma unroll
        for (int j = 0; j < TN; j++) acc[i][j] = 0.f;

    for (int k0 = 0; k0 < K; k0 += BK) {
        // load A tile (BM x BK) as float4, store transposed As[k][m]
        for (int n = tid; n < (BM * BK) / 4; n += 256) {
            int row = n / (BK / 4);
            int cb  = n % (BK / 4);
            float4 v = *(const float4*)(A + (size_t)(bm + row) * K + k0 + cb * 4);
            As[cb * 4 + 0][row] = v.x;
            As[cb * 4 + 1][row] = v.y;
            As[cb * 4 + 2][row] = v.z;
            As[cb * 4 + 3][row] = v.w;
        }
        for (int n = tid; n < (BN * BK) / 4; n += 256) {
            int row = n / (BK / 4);
            int cb  = n % (BK / 4);
            float4 v = *(const float4*)(W + (size_t)(bn + row) * K + k0 + cb * 4);
            Ws[cb * 4 + 0][row] = v.x;
            Ws[cb * 4 + 1][row] = v.y;
            Ws[cb * 4 + 2][row] = v.z;
            Ws[cb * 4 + 3][row] = v.w;
        }
        __syncthreads();

#pragma unroll
        for (int kk = 0; kk < BK; kk++) {
            float a[TM], b[TN];
#pragma unroll
            for (int i = 0; i < TM; i++) a[i] = As[kk][ty * TM + i];
#pragma unroll
            for (int j = 0; j < TN; j++) b[j] = Ws[kk][tx * TN + j];
#pragma unroll
            for (int i = 0; i < TM; i++)
#pragma unroll
                for (int j = 0; j < TN; j++)
                    acc[i][j] = fmaf(a[i], b[j], acc[i][j]);
        }
        __syncthreads();
    }

#pragma unroll
    for (int i = 0; i < TM; i++) {
        int m = bm + ty * TM + i;
#pragma unroll
        for (int j = 0; j < TN; j++) {
            int n = bn + tx * TN + j;
            float v = acc[i][j] + bias[n];
            if (SELU_ACT) v = selu_f(v);
            C[(size_t)m * N + n] = v;
        }
    }
}

// ---------------- Cholesky (+ optional inverse & logdet) ----------------
// blocks 0..255:   L = chol(cov_k + eps I) -> Linv (lower, upper zeroed), logdet
// blocks 256..511: L = chol(cov_k)         -> Lraw (lower, upper zeroed)
__global__ void chol_kernel(const float* __restrict__ cov) {
    __shared__ float Ls[EMB][EMB + 1];
    __shared__ float Inv[EMB][EMB + 1];

    const int k   = blockIdx.x & (KC - 1);
    const bool raw = blockIdx.x >= KC;
    const int i = threadIdx.x;   // 0..63
    const float* A = cov + (size_t)k * EMB * EMB;

    for (int j = 0; j < EMB; j++) Ls[i][j] = A[i * EMB + j];
    if (!raw) Ls[i][i] += 0.005f;
    __syncthreads();

    for (int j = 0; j < EMB; j++) {
        if (i == j) {
            float s = Ls[j][j];
            for (int t = 0; t < j; t++) s -= Ls[j][t] * Ls[j][t];
            Ls[j][j] = sqrtf(s);
        }
        __syncthreads();
        if (i > j) {
            float s = Ls[i][j];
            for (int t = 0; t < j; t++) s -= Ls[i][t] * Ls[j][t];
            Ls[i][j] = s / Ls[j][j];
        }
        __syncthreads();
    }

    if (raw) {
        float* out = g_Lraw + (size_t)k * EMB * EMB;
        for (int j = 0; j < EMB; j++) out[i * EMB + j] = (j <= i) ? Ls[i][j] : 0.f;
    } else {
        if (i == 0) {
            float ld = 0.f;
            for (int t = 0; t < EMB; t++) ld += logf(Ls[t][t]);
            g_logdet[k] = 2.f * ld;
        }
        // thread i = column c of L^{-1}: forward substitution (independent per column)
        const int c = i;
        for (int r = 0; r < EMB; r++) {
            if (r < c) { Inv[r][c] = 0.f; continue; }
            float s = (r == c) ? 1.f : 0.f;
            for (int t = c; t < r; t++) s -= Ls[r][t] * Inv[t][c];
            Inv[r][c] = s / Ls[r][r];
        }
        __syncthreads();
        float* out = g_Linv + (size_t)k * EMB * EMB;
        for (int j = 0; j < EMB; j++) out[i * EMB + j] = Inv[i][j];
    }
}

// ---------------- log-probs: grid (b-tiles of 128, K), block 128 ----------------
__global__ void __launch_bounds__(128) logprob_kernel(
    const float* __restrict__ means, const float* __restrict__ sizes)
{
    __shared__ float sLinv[EMB * EMB];
    __shared__ float smean[EMB];

    const int k = blockIdx.y;
    const int b = blockIdx.x * 128 + threadIdx.x;
    const float* Lk = g_Linv + (size_t)k * EMB * EMB;

    for (int i = threadIdx.x; i < (EMB * EMB) / 4; i += 128)
        ((float4*)sLinv)[i] = ((const float4*)Lk)[i];
    if (threadIdx.x < EMB) smean[threadIdx.x] = means[k * EMB + threadIdx.x];
    __syncthreads();

    float diff[EMB];
    const float4* er = (const float4*)(g_enc + (size_t)b * EMB);
#pragma unroll
    for (int t = 0; t < EMB / 4; t++) {
        float4 e = er[t];
        diff[4 * t + 0] = e.x - smean[4 * t + 0];
        diff[4 * t + 1] = e.y - smean[4 * t + 1];
        diff[4 * t + 2] = e.z - smean[4 * t + 2];
        diff[4 * t + 3] = e.w - smean[4 * t + 3];
    }

    float quad = 0.f;
#pragma unroll
    for (int d = 0; d < EMB; d++) {
        float s = 0.f;
#pragma unroll
        for (int t4 = 0; t4 <= d; t4 += 4) {   // upper part of Linv is zero -> safe padding
            float4 lv = *(const float4*)(sLinv + d * EMB + t4);
            s += lv.x * diff[t4 + 0];
            s += lv.y * diff[t4 + 1];
            s += lv.z * diff[t4 + 2];
            s += lv.w * diff[t4 + 3];
        }
        quad += s * s;
    }

    const float LOG2PI = 1.8378770664093453f;
    float lp = logf(sizes[k]) - 0.5f * (64.f * LOG2PI + g_logdet[k]) - 0.5f * quad;
    g_lp[(size_t)b * KC + k] = lp;
}

// ---------------- argmax over K per row (one warp per row) ----------------
__global__ void argmax_kernel() {
    int gwarp = (blockIdx.x * blockDim.x + threadIdx.x) >> 5;
    int lane  = threadIdx.x & 31;
    if (gwarp >= BATCH) return;

    float best = -INFINITY;
    int bi = 0;
    const float* row = g_lp + (size_t)gwarp * KC;
    for (int k = lane; k < KC; k += 32) {
        float v = row[k];
        if (v > best || (v == best && k < bi)) { best = v; bi = k; }
    }
#pragma unroll
    for (int off = 16; off; off >>= 1) {
        float ov = __shfl_down_sync(0xffffffffu, best, off);
        int   oi = __shfl_down_sync(0xffffffffu, bi, off);
        if (ov > best || (ov == best && oi < bi)) { best = ov; bi = oi; }
    }
    if (lane == 0) g_idx[gwarp] = bi;
}

// ---------------- sample: quantized[b] = means[idx] + Lraw[idx] @ noise[b] ----------------
__global__ void __launch_bounds__(64) sample_kernel(
    const float* __restrict__ noise, const float* __restrict__ means)
{
    __shared__ float sL[EMB * EMB];
    __shared__ float sn[EMB];
    const int b = blockIdx.x;
    const int t = threadIdx.x;
    const int k = g_idx[b];
    const float* L = g_Lraw + (size_t)k * EMB * EMB;

    for (int i = t; i < (EMB * EMB) / 4; i += 64)
        ((float4*)sL)[i] = ((const float4*)L)[i];
    sn[t] = noise[(size_t)b * EMB + t];
    __syncthreads();

    float s = means[k * EMB + t];
    for (int j = 0; j <= t; j++) s += sL[t * EMB + j] * sn[j];
    g_quant[(size_t)b * EMB + t] = s;   // straight-through: forward value == sample
}

// ---------------- pack log_probs + idx into output tail ----------------
__global__ void pack_kernel(float* __restrict__ out, int out_size) {
    const int LP_OFF  = BATCH * IN_DIM;           // 4194304
    const int IDX_OFF = LP_OFF + BATCH * KC;      // 6291456
    int i = blockIdx.x * blockDim.x + threadIdx.x;
    if (out_size >= IDX_OFF && i < BATCH * KC)
        out[LP_OFF + i] = g_lp[i];
    if (out_size >= IDX_OFF + BATCH && i < BATCH)
        out[IDX_OFF + i] = (float)g_idx[i];
}

// ---------------- launch ----------------
extern "C" void kernel_launch(void* const* d_in, const int* in_sizes, int n_in,
                              void* d_out, int out_size)
{
    const float* x     = (const float*)d_in[0];
    const float* noise = (const float*)d_in[1];
    const float* eW1 = (const float*)d_in[2];
    const float* eb1 = (const float*)d_in[3];
    const float* eW2 = (const float*)d_in[4];
    const float* eb2 = (const float*)d_in[5];
    const float* eW3 = (const float*)d_in[6];
    const float* eb3 = (const float*)d_in[7];
    const float* dW1 = (const float*)d_in[8];
    const float* db1 = (const float*)d_in[9];
    const float* dW2 = (const float*)d_in[10];
    const float* db2 = (const float*)d_in[11];
    const float* dW3 = (const float*)d_in[12];
    const float* db3 = (const float*)d_in[13];
    const float* means = (const float*)d_in[14];
    const float* sizes = (const float*)d_in[15];
    const float* cov   = (const float*)d_in[16];
    float* out = (float*)d_out;

    float *h1, *h2, *enc, *quant;
    cudaGetSymbolAddress((void**)&h1, g_h1);
    cudaGetSymbolAddress((void**)&h2, g_h2);
    cudaGetSymbolAddress((void**)&enc, g_enc);
    cudaGetSymbolAddress((void**)&quant, g_quant);

    // GMM prep (independent of encoder — launch first)
    chol_kernel<<<2 * KC, EMB>>>(cov);

    // encoder
    sgemm_kernel<128, 128, 8, 8, 8, true><<<dim3(DENSE / 128, BATCH / 128), 256>>>(
        x, eW1, eb1, h1, BATCH, DENSE, IN_DIM);
    sgemm_kernel<128, 128, 8, 8, 8, true><<<dim3(DENSE / 128, BATCH / 128), 256>>>(
        h1, eW2, eb2, h2, BATCH, DENSE, DENSE);
    sgemm_kernel<64, 64, 16, 4, 4, false><<<dim3(EMB / 64, BATCH / 64), 256>>>(
        h2, eW3, eb3, enc, BATCH, EMB, DENSE);

    // GMM log-probs + argmax + sample
    logprob_kernel<<<dim3(BATCH / 128, KC), 128>>>(means, sizes);
    argmax_kernel<<<(BATCH * 32) / 256, 256>>>();
    sample_kernel<<<BATCH, EMB>>>(noise, means);

    // decoder (dec straight into out[0 .. B*IN_DIM))
    sgemm_kernel<128, 128, 8, 8, 8, true><<<dim3(DENSE / 128, BATCH / 128), 256>>>(
        quant, dW1, db1, h1, BATCH, DENSE, EMB);
    sgemm_kernel<128, 128, 8, 8, 8, true><<<dim3(DENSE / 128, BATCH / 128), 256>>>(
        h1, dW2, db2, h2, BATCH, DENSE, DENSE);
    sgemm_kernel<128, 128, 8, 8, 8, false><<<dim3(IN_DIM / 128, BATCH / 128), 256>>>(
        h2, dW3, db3, out, BATCH, IN_DIM, DENSE);

    // tail outputs
    pack_kernel<<<(BATCH * KC + 255) / 256, 256>>>(out, out_size);
}

// round 4
// speedup vs baseline: 1.8822x; 1.8803x over previous
#include <cuda_runtime.h>
#include <cuda_bf16.h>
#include <math.h>
#include <stdint.h>

#define BATCH   8192
#define IN_DIM  512
#define EMB     64
#define KC      256
#define DENSE   1152

// ---------------- scratch (device globals; no allocation allowed) ----------------
__device__ __align__(128) __nv_bfloat16 g_xs  [BATCH * 3 * IN_DIM];
__device__ __align__(128) __nv_bfloat16 g_h1s [BATCH * 3 * DENSE];
__device__ __align__(128) __nv_bfloat16 g_h2s [BATCH * 3 * DENSE];
__device__ __align__(128) __nv_bfloat16 g_qs  [BATCH * 3 * EMB];
__device__ __align__(128) __nv_bfloat16 g_eW1s[DENSE * 3 * IN_DIM];
__device__ __align__(128) __nv_bfloat16 g_eW2s[DENSE * 3 * DENSE];
__device__ __align__(128) __nv_bfloat16 g_eW3s[EMB   * 3 * DENSE];
__device__ __align__(128) __nv_bfloat16 g_dW1s[DENSE * 3 * EMB];
__device__ __align__(128) __nv_bfloat16 g_dW2s[DENSE * 3 * DENSE];
__device__ __align__(128) __nv_bfloat16 g_dW3s[IN_DIM* 3 * DENSE];
__device__ float g_enc [BATCH * EMB];
__device__ float g_Linv[KC * EMB * EMB];
__device__ float g_Lraw[KC * EMB * EMB];
__device__ float g_logdet[KC];
__device__ float g_lp  [BATCH * KC];
__device__ int   g_idx [BATCH];

// ---------------- small helpers ----------------
__device__ __forceinline__ float selu_f(float x) {
    const float scale = 1.0507009873554805f;
    const float alpha = 1.6732632423543772f;
    return scale * (x > 0.f ? x : alpha * expm1f(x));
}
__device__ __forceinline__ void split2(float v, __nv_bfloat16& hi, __nv_bfloat16& lo) {
    hi = __float2bfloat16(v);
    lo = __float2bfloat16(v - __bfloat162float(hi));
}
__device__ __forceinline__ uint32_t pack_bf2(__nv_bfloat16 a, __nv_bfloat16 b) {
    __nv_bfloat162 t; t.x = a; t.y = b;
    return *reinterpret_cast<uint32_t*>(&t);
}
__device__ __forceinline__ uint32_t smem_u32(const void* p) {
    uint32_t a;
    asm("{ .reg .u64 t; cvta.to.shared.u64 t, %1; cvt.u32.u64 %0, t; }" : "=r"(a) : "l"(p));
    return a;
}
__device__ __forceinline__ void cp16(uint32_t dst, const void* src) {
    asm volatile("cp.async.cg.shared.global [%0], [%1], 16;" :: "r"(dst), "l"(src));
}
__device__ __forceinline__ uint32_t sw128(uint32_t off) { return off ^ ((off >> 3) & 0x70); }

__device__ __forceinline__ void ldsm4(uint32_t& r0, uint32_t& r1, uint32_t& r2, uint32_t& r3,
                                      uint32_t addr) {
    asm volatile("ldmatrix.sync.aligned.m8n8.x4.shared.b16 {%0,%1,%2,%3}, [%4];"
        : "=r"(r0), "=r"(r1), "=r"(r2), "=r"(r3) : "r"(addr));
}
__device__ __forceinline__ void mma16816(float* c,
    uint32_t a0, uint32_t a1, uint32_t a2, uint32_t a3, uint32_t b0, uint32_t b1) {
    asm volatile("mma.sync.aligned.m16n8k16.row.col.f32.bf16.bf16.f32 "
        "{%0,%1,%2,%3}, {%4,%5,%6,%7}, {%8,%9}, {%0,%1,%2,%3};"
        : "+f"(c[0]), "+f"(c[1]), "+f"(c[2]), "+f"(c[3])
        : "r"(a0), "r"(a1), "r"(a2), "r"(a3), "r"(b0), "r"(b1));
}

// ---------------- split conversions ----------------
// A-side: row r of length K -> [hi | hi | lo] (row length 3K)
__global__ void split_a_kernel(const float* __restrict__ in, __nv_bfloat16* __restrict__ out,
                               int total, int K) {
    int i = blockIdx.x * blockDim.x + threadIdx.x;
    if (i >= total) return;
    int r = i / K, c = i % K;
    __nv_bfloat16 h, l; split2(in[i], h, l);
    size_t b = (size_t)r * 3 * K;
    out[b + c] = h; out[b + K + c] = h; out[b + 2 * K + c] = l;
}
// W-side: [hi | lo | hi]
__global__ void split_w_kernel(const float* __restrict__ in, __nv_bfloat16* __restrict__ out,
                               int total, int K) {
    int i = blockIdx.x * blockDim.x + threadIdx.x;
    if (i >= total) return;
    int r = i / K, c = i % K;
    __nv_bfloat16 h, l; split2(in[i], h, l);
    size_t b = (size_t)r * 3 * K;
    out[b + c] = h; out[b + K + c] = l; out[b + 2 * K + c] = h;
}

// ================= tensor-core GEMM via mma.sync (sm_80+ path) =================
// C = A'[M,K3] @ W'[N,K3]^T (+bias). MODE 0: fp32 out. MODE 1: SELU + split-triple
// bf16 out, row stride 3N (planes [hi|hi|lo]).
// BM=128, BK=64 (=128B rows, SW128 swizzle). 256 threads, 8 warps: 4(m) x 2(n),
// warp tile 32 x (BN/2). Double-buffered cp.async.
template<int BN, int MODE>
__global__ void __launch_bounds__(256) mma_gemm(
    const __nv_bfloat16* __restrict__ A, const __nv_bfloat16* __restrict__ W,
    const float* __restrict__ bias, void* __restrict__ Cout,
    int N, int K3)
{
    constexpr int BM = 128;
    constexpr int ABYTES = BM * 128;
    constexpr int BBYTES = BN * 128;
    constexpr int BUF = ABYTES + BBYTES;
    constexpr int NF = BN / 16;              // n-frags (8 cols) per warp

    extern __shared__ __align__(1024) char smem[];
    const uint32_t sbase = smem_u32(smem);

    const int tid = threadIdx.x;
    const int lane = tid & 31;
    const int wid = tid >> 5;
    const int wm = wid & 3;                  // m quadrant: rows wm*32
    const int wn = wid >> 2;                 // n half: cols wn*(BN/2)
    const int bm = blockIdx.y * BM;
    const int bn = blockIdx.x * BN;

    float acc[2][NF][4];
#pragma unroll
    for (int i = 0; i < 2; i++)
#pragma unroll
        for (int j = 0; j < NF; j++)
#pragma unroll
            for (int c = 0; c < 4; c++) acc[i][j][c] = 0.f;

    const int nk = K3 >> 6;

    auto load_tile = [&](int ck, int b) {
        const uint32_t aB = sbase + (uint32_t)b * BUF;
        const uint32_t bB = aB + ABYTES;
        const __nv_bfloat16* Ap = A + (size_t)bm * K3 + ck * 64;
        const __nv_bfloat16* Wq = W + (size_t)bn * K3 + ck * 64;
#pragma unroll
        for (int t = 0; t < (BM * 8) / 256; t++) {
            int idx = tid + t * 256;
            int r = idx >> 3, c = idx & 7;
            cp16(aB + sw128((uint32_t)(r * 128 + c * 16)), Ap + (size_t)r * K3 + c * 8);
        }
#pragma unroll
        for (int t = 0; t < (BN * 8) / 256; t++) {
            int idx = tid + t * 256;
            int r = idx >> 3, c = idx & 7;
            cp16(bB + sw128((uint32_t)(r * 128 + c * 16)), Wq + (size_t)r * K3 + c * 8);
        }
        asm volatile("cp.async.commit_group;" ::: "memory");
    };

    // per-thread ldmatrix row offsets (within tile)
    const int ar = wm * 32 + (lane & 15);    // A row for mi=0 (mi=1 -> +16)
    const int br = wn * (BN / 2) + (lane & 15); // B row for nf2=0 (nf2 -> +16*nf2)
    const int kh = (lane >> 4) * 16;         // 16B half-select within 32B k-step

    load_tile(0, 0);

    for (int ck = 0; ck < nk; ck++) {
        const int b = ck & 1;
        if (ck + 1 < nk) {
            load_tile(ck + 1, b ^ 1);
            asm volatile("cp.async.wait_group 1;" ::: "memory");
        } else {
            asm volatile("cp.async.wait_group 0;" ::: "memory");
        }
        __syncthreads();

        const uint32_t aB = sbase + (uint32_t)b * BUF;
        const uint32_t bB = aB + ABYTES;
#pragma unroll
        for (int ks = 0; ks < 4; ks++) {
            const uint32_t kcol = (uint32_t)(ks * 32 + kh);
            uint32_t a0[4], a1[4];
            ldsm4(a0[0], a0[1], a0[2], a0[3], aB + sw128((uint32_t)(ar * 128) + kcol));
            ldsm4(a1[0], a1[1], a1[2], a1[3], aB + sw128((uint32_t)((ar + 16) * 128) + kcol));
            uint32_t bf[NF][2];
#pragma unroll
            for (int p = 0; p < NF / 2; p++) {
                uint32_t r0, r1, r2, r3;
                ldsm4(r0, r1, r2, r3, bB + sw128((uint32_t)((br + p * 16) * 128) + kcol));
                bf[2 * p][0] = r0; bf[2 * p][1] = r2;
                bf[2 * p + 1][0] = r1; bf[2 * p + 1][1] = r3;
            }
#pragma unroll
            for (int nf = 0; nf < NF; nf++) {
                mma16816(acc[0][nf], a0[0], a0[1], a0[2], a0[3], bf[nf][0], bf[nf][1]);
                mma16816(acc[1][nf], a1[0], a1[1], a1[2], a1[3], bf[nf][0], bf[nf][1]);
            }
        }
        __syncthreads();
    }

    // ---- epilogue ----
    const int row0 = bm + wm * 32 + (lane >> 2);
    const int colb = bn + wn * (BN / 2) + (lane & 3) * 2;
#pragma unroll
    for (int mi = 0; mi < 2; mi++) {
#pragma unroll
        for (int nf = 0; nf < NF; nf++) {
            const int col = colb + nf * 8;
            const float b0 = bias[col], b1 = bias[col + 1];
#pragma unroll
            for (int h = 0; h < 2; h++) {     // h=0 -> c0,c1 ; h=1 -> c2,c3 (row+8)
                const int m = row0 + mi * 16 + h * 8;
                float v0 = acc[mi][nf][2 * h + 0] + b0;
                float v1 = acc[mi][nf][2 * h + 1] + b1;
                if (MODE == 0) {
                    float2 o; o.x = v0; o.y = v1;
                    *(float2*)((float*)Cout + (size_t)m * N + col) = o;
                } else {
                    v0 = selu_f(v0); v1 = selu_f(v1);
                    __nv_bfloat16 h0, l0, h1, l1;
                    split2(v0, h0, l0); split2(v1, h1, l1);
                    uint32_t hh = pack_bf2(h0, h1);
                    uint32_t ll = pack_bf2(l0, l1);
                    __nv_bfloat16* C = (__nv_bfloat16*)Cout;
                    const size_t base = (size_t)m * (3 * (size_t)N) + col;
                    *(uint32_t*)(C + base)         = hh;
                    *(uint32_t*)(C + base + N)     = hh;
                    *(uint32_t*)(C + base + 2 * N) = ll;
                }
            }
        }
    }
}

// ---------------- Cholesky (+ inverse & logdet) — exact fp32 ----------------
__global__ void chol_kernel(const float* __restrict__ cov) {
    __shared__ float Ls[EMB][EMB + 1];
    __shared__ float Inv[EMB][EMB + 1];
    const int k = blockIdx.x & (KC - 1);
    const bool raw = blockIdx.x >= KC;
    const int i = threadIdx.x;
    const float* A = cov + (size_t)k * EMB * EMB;
    for (int j = 0; j < EMB; j++) Ls[i][j] = A[i * EMB + j];
    if (!raw) Ls[i][i] += 0.005f;
    __syncthreads();
    for (int j = 0; j < EMB; j++) {
        if (i == j) {
            float s = Ls[j][j];
            for (int t = 0; t < j; t++) s -= Ls[j][t] * Ls[j][t];
            Ls[j][j] = sqrtf(s);
        }
        __syncthreads();
        if (i > j) {
            float s = Ls[i][j];
            for (int t = 0; t < j; t++) s -= Ls[i][t] * Ls[j][t];
            Ls[i][j] = s / Ls[j][j];
        }
        __syncthreads();
    }
    if (raw) {
        float* out = g_Lraw + (size_t)k * EMB * EMB;
        for (int j = 0; j < EMB; j++) out[i * EMB + j] = (j <= i) ? Ls[i][j] : 0.f;
    } else {
        if (i == 0) {
            float ld = 0.f;
            for (int t = 0; t < EMB; t++) ld += logf(Ls[t][t]);
            g_logdet[k] = 2.f * ld;
        }
        const int c = i;
        for (int r = 0; r < EMB; r++) {
            if (r < c) { Inv[r][c] = 0.f; continue; }
            float s = (r == c) ? 1.f : 0.f;
            for (int t = c; t < r; t++) s -= Ls[r][t] * Inv[t][c];
            Inv[r][c] = s / Ls[r][r];
        }
        __syncthreads();
        float* out = g_Linv + (size_t)k * EMB * EMB;
        for (int j = 0; j < EMB; j++) out[i * EMB + j] = Inv[i][j];
    }
}

// ---------------- log-probs (exact fp32) ----------------
__global__ void __launch_bounds__(128) logprob_kernel(
    const float* __restrict__ means, const float* __restrict__ sizes)
{
    __shared__ float sLinv[EMB * EMB];
    __shared__ float smean[EMB];
    const int k = blockIdx.y;
    const int b = blockIdx.x * 128 + threadIdx.x;
    const float* Lk = g_Linv + (size_t)k * EMB * EMB;
    for (int i = threadIdx.x; i < (EMB * EMB) / 4; i += 128)
        ((float4*)sLinv)[i] = ((const float4*)Lk)[i];
    if (threadIdx.x < EMB) smean[threadIdx.x] = means[k * EMB + threadIdx.x];
    __syncthreads();
    float diff[EMB];
    const float4* er = (const float4*)(g_enc + (size_t)b * EMB);
#pragma unroll
    for (int t = 0; t < EMB / 4; t++) {
        float4 e = er[t];
        diff[4 * t + 0] = e.x - smean[4 * t + 0];
        diff[4 * t + 1] = e.y - smean[4 * t + 1];
        diff[4 * t + 2] = e.z - smean[4 * t + 2];
        diff[4 * t + 3] = e.w - smean[4 * t + 3];
    }
    float quad = 0.f;
#pragma unroll
    for (int d = 0; d < EMB; d++) {
        float s = 0.f;
#pragma unroll
        for (int t4 = 0; t4 <= d; t4 += 4) {
            float4 lv = *(const float4*)(sLinv + d * EMB + t4);
            s += lv.x * diff[t4 + 0];
            s += lv.y * diff[t4 + 1];
            s += lv.z * diff[t4 + 2];
            s += lv.w * diff[t4 + 3];
        }
        quad += s * s;
    }
    const float LOG2PI = 1.8378770664093453f;
    g_lp[(size_t)b * KC + k] =
        logf(sizes[k]) - 0.5f * (64.f * LOG2PI + g_logdet[k]) - 0.5f * quad;
}

// ---------------- argmax ----------------
__global__ void argmax_kernel() {
    int gwarp = (blockIdx.x * blockDim.x + threadIdx.x) >> 5;
    int lane = threadIdx.x & 31;
    if (gwarp >= BATCH) return;
    float best = -INFINITY; int bi = 0;
    const float* row = g_lp + (size_t)gwarp * KC;
    for (int k = lane; k < KC; k += 32) {
        float v = row[k];
        if (v > best || (v == best && k < bi)) { best = v; bi = k; }
    }
#pragma unroll
    for (int off = 16; off; off >>= 1) {
        float ov = __shfl_down_sync(0xffffffffu, best, off);
        int   oi = __shfl_down_sync(0xffffffffu, bi, off);
        if (ov > best || (ov == best && oi < bi)) { best = ov; bi = oi; }
    }
    if (lane == 0) g_idx[gwarp] = bi;
}

// ---------------- sample -> split-triple bf16 for decoder input ----------------
__global__ void __launch_bounds__(64) sample_kernel(
    const float* __restrict__ noise, const float* __restrict__ means)
{
    __shared__ float sL[EMB * EMB];
    __shared__ float sn[EMB];
    const int b = blockIdx.x;
    const int t = threadIdx.x;
    const int k = g_idx[b];
    const float* L = g_Lraw + (size_t)k * EMB * EMB;
    for (int i = t; i < (EMB * EMB) / 4; i += 64)
        ((float4*)sL)[i] = ((const float4*)L)[i];
    sn[t] = noise[(size_t)b * EMB + t];
    __syncthreads();
    float s = means[k * EMB + t];
    for (int j = 0; j <= t; j++) s += sL[t * EMB + j] * sn[j];
    __nv_bfloat16 h, l; split2(s, h, l);
    size_t base = (size_t)b * 3 * EMB;
    g_qs[base + t] = h; g_qs[base + EMB + t] = h; g_qs[base + 2 * EMB + t] = l;
}

// ---------------- pack log_probs + idx ----------------
__global__ void pack_kernel(float* __restrict__ out, int out_size) {
    const int LP_OFF  = BATCH * IN_DIM;
    const int IDX_OFF = LP_OFF + BATCH * KC;
    int i = blockIdx.x * blockDim.x + threadIdx.x;
    if (out_size >= IDX_OFF && i < BATCH * KC) out[LP_OFF + i] = g_lp[i];
    if (out_size >= IDX_OFF + BATCH && i < BATCH) out[IDX_OFF + i] = (float)g_idx[i];
}

// ---------------- launch ----------------
extern "C" void kernel_launch(void* const* d_in, const int* in_sizes, int n_in,
                              void* d_out, int out_size)
{
    const float* x   = (const float*)d_in[0];
    const float* noi = (const float*)d_in[1];
    const float* eW1 = (const float*)d_in[2];
    const float* eb1 = (const float*)d_in[3];
    const float* eW2 = (const float*)d_in[4];
    const float* eb2 = (const float*)d_in[5];
    const float* eW3 = (const float*)d_in[6];
    const float* eb3 = (const float*)d_in[7];
    const float* dW1 = (const float*)d_in[8];
    const float* db1 = (const float*)d_in[9];
    const float* dW2 = (const float*)d_in[10];
    const float* db2 = (const float*)d_in[11];
    const float* dW3 = (const float*)d_in[12];
    const float* db3 = (const float*)d_in[13];
    const float* means = (const float*)d_in[14];
    const float* sizes = (const float*)d_in[15];
    const float* cov   = (const float*)d_in[16];
    float* out = (float*)d_out;

    __nv_bfloat16 *xs, *h1s, *h2s, *qs, *ew1s, *ew2s, *ew3s, *dw1s, *dw2s, *dw3s;
    float *enc;
    cudaGetSymbolAddress((void**)&xs,  g_xs);
    cudaGetSymbolAddress((void**)&h1s, g_h1s);
    cudaGetSymbolAddress((void**)&h2s, g_h2s);
    cudaGetSymbolAddress((void**)&qs,  g_qs);
    cudaGetSymbolAddress((void**)&ew1s, g_eW1s);
    cudaGetSymbolAddress((void**)&ew2s, g_eW2s);
    cudaGetSymbolAddress((void**)&ew3s, g_eW3s);
    cudaGetSymbolAddress((void**)&dw1s, g_dW1s);
    cudaGetSymbolAddress((void**)&dw2s, g_dW2s);
    cudaGetSymbolAddress((void**)&dw3s, g_dW3s);
    cudaGetSymbolAddress((void**)&enc, g_enc);

    const int SM128 = 2 * (128 * 128 + 128 * 128);   // 65536
    const int SM64  = 2 * (128 * 128 + 64 * 128);    // 49152
    cudaFuncSetAttribute(mma_gemm<128, 1>, cudaFuncAttributeMaxDynamicSharedMemorySize, SM128);
    cudaFuncSetAttribute(mma_gemm<128, 0>, cudaFuncAttributeMaxDynamicSharedMemorySize, SM128);
    cudaFuncSetAttribute(mma_gemm<64, 0>,  cudaFuncAttributeMaxDynamicSharedMemorySize, SM64);

    // GMM prep + operand conversions
    chol_kernel<<<2 * KC, EMB>>>(cov);
    split_a_kernel<<<(BATCH * IN_DIM + 255) / 256, 256>>>(x, xs, BATCH * IN_DIM, IN_DIM);
    split_w_kernel<<<(DENSE * IN_DIM + 255) / 256, 256>>>(eW1, ew1s, DENSE * IN_DIM, IN_DIM);
    split_w_kernel<<<(DENSE * DENSE + 255) / 256, 256>>>(eW2, ew2s, DENSE * DENSE, DENSE);
    split_w_kernel<<<(EMB * DENSE + 255) / 256, 256>>>(eW3, ew3s, EMB * DENSE, DENSE);
    split_w_kernel<<<(DENSE * EMB + 255) / 256, 256>>>(dW1, dw1s, DENSE * EMB, EMB);
    split_w_kernel<<<(DENSE * DENSE + 255) / 256, 256>>>(dW2, dw2s, DENSE * DENSE, DENSE);
    split_w_kernel<<<(IN_DIM * DENSE + 255) / 256, 256>>>(dW3, dw3s, IN_DIM * DENSE, DENSE);

    // encoder
    mma_gemm<128, 1><<<dim3(DENSE / 128, BATCH / 128), 256, SM128>>>(
        xs, ew1s, eb1, h1s, DENSE, 3 * IN_DIM);
    mma_gemm<128, 1><<<dim3(DENSE / 128, BATCH / 128), 256, SM128>>>(
        h1s, ew2s, eb2, h2s, DENSE, 3 * DENSE);
    mma_gemm<64, 0><<<dim3(EMB / 64, BATCH / 128), 256, SM64>>>(
        h2s, ew3s, eb3, enc, EMB, 3 * DENSE);

    // GMM
    logprob_kernel<<<dim3(BATCH / 128, KC), 128>>>(means, sizes);
    argmax_kernel<<<(BATCH * 32) / 256, 256>>>();
    sample_kernel<<<BATCH, EMB>>>(noi, means);

    // decoder
    mma_gemm<128, 1><<<dim3(DENSE / 128, BATCH / 128), 256, SM128>>>(
        qs, dw1s, db1, h1s, DENSE, 3 * EMB);
    mma_gemm<128, 1><<<dim3(DENSE / 128, BATCH / 128), 256, SM128>>>(
        h1s, dw2s, db2, h2s, DENSE, 3 * DENSE);
    mma_gemm<128, 0><<<dim3(IN_DIM / 128, BATCH / 128), 256, SM128>>>(
        h2s, dw3s, db3, out, IN_DIM, 3 * DENSE);

    pack_kernel<<<(BATCH * KC + 255) / 256, 256>>>(out, out_size);
}